// round 13
// baseline (speedup 1.0000x reference)
#include <cuda_runtime.h>

// Problem constants (fixed by the dataset)
#define NB   64          // batch
#define T1   4097        // maxT+1
#define MAXT 4096
#define HB   16          // hidden states
#define NA   18          // actions
#define CL   32          // chunk length (steps per chunk)
#define D    8           // steps per phase
#define PH   4           // phases per chunk (CL / D)
#define BPB  16          // blocks per batch
#define NMB  16          // block-level matrices per batch

#define RSTRIDE 292      // padded row stride in floats (1168B, 16B aligned)

// Scratch: per (batch, block) folded transfer matrix (256 steps each).
__device__ float g_mats[NB * NMB * HB * HB];   // 1 MB
__device__ float g_lam[NB * NMB * HB];
__device__ float g_partial[NB];
__device__ int   g_cnt[NB];     // zero-init; self-resetting each call
__device__ int   g_cnt2;        // zero-init; self-resetting each call

__device__ __forceinline__ float ldcg(const float* p) {
    float v; asm volatile("ld.global.cg.f32 %0,[%1];" : "=f"(v) : "l"(p)); return v;
}
__device__ __forceinline__ float4 ldcg4(const float* p) {
    float4 v;
    asm volatile("ld.global.cg.v4.f32 {%0,%1,%2,%3},[%4];"
                 : "=f"(v.x), "=f"(v.y), "=f"(v.z), "=f"(v.w) : "l"(p));
    return v;
}

#define CP_ASYNC16(dst, src) \
    asm volatile("cp.async.cg.shared.global [%0], [%1], 16;" :: "r"(dst), "l"(src))
#define CP_COMMIT() asm volatile("cp.async.commit_group;" ::: "memory")
#define CP_WAIT(n)  asm volatile("cp.async.wait_group %0;" :: "n"(n) : "memory")

// Tree product: C_true = A_true * P_true (A later, P earlier).
__device__ __forceinline__ void mat_product2(
    const float* __restrict__ srcM, const float* __restrict__ srcLam,
    float* __restrict__ dstM, float* __restrict__ dstLam,
    int pidx, int lane, float* __restrict__ sw, bool from_gmem)
{
    const int c = lane & 15;
    const int h = lane >> 4;                    // rows [8h, 8h+8)
    const float* Pm = srcM + (size_t)(2 * pidx) * 256;
    const float* Am = srcM + (size_t)(2 * pidx + 1) * 256;
    float lamP, lamA;
    if (from_gmem) {
        lamP = ldcg(srcLam + (2 * pidx) * 16 + c);
        lamA = ldcg(srcLam + (2 * pidx + 1) * 16 + c);
    } else {
        lamP = srcLam[(2 * pidx) * 16 + c];
        lamA = srcLam[(2 * pidx + 1) * 16 + c];
    }
    float mA = lamA;
    mA = fmaxf(mA, __shfl_xor_sync(0xffffffffu, mA, 1));
    mA = fmaxf(mA, __shfl_xor_sync(0xffffffffu, mA, 2));
    mA = fmaxf(mA, __shfl_xor_sync(0xffffffffu, mA, 4));
    mA = fmaxf(mA, __shfl_xor_sync(0xffffffffu, mA, 8));
    if (lane < 16) sw[c] = __expf(lamA - mA);
    __syncwarp();
    float w[16];
#pragma unroll
    for (int j = 0; j < 16; ++j)
        w[j] = sw[j] * (from_gmem ? ldcg(Pm + j * 16 + c) : Pm[j * 16 + c]);
    __syncwarp();
    float Cv[8];
#pragma unroll
    for (int k8 = 0; k8 < 8; ++k8) {
        float4 a0, a1, a2, a3;
        const float* Ar = Am + (h * 8 + k8) * 16;
        if (from_gmem) { a0 = ldcg4(Ar); a1 = ldcg4(Ar + 4); a2 = ldcg4(Ar + 8); a3 = ldcg4(Ar + 12); }
        else { const float4* A4 = (const float4*)Ar; a0 = A4[0]; a1 = A4[1]; a2 = A4[2]; a3 = A4[3]; }
        float d0 = fmaf(a0.x, w[0],  a0.y * w[1])  + fmaf(a0.z, w[2],  a0.w * w[3]);
        float d1 = fmaf(a1.x, w[4],  a1.y * w[5])  + fmaf(a1.z, w[6],  a1.w * w[7]);
        float d2 = fmaf(a2.x, w[8],  a2.y * w[9])  + fmaf(a2.z, w[10], a2.w * w[11]);
        float d3 = fmaf(a3.x, w[12], a3.y * w[13]) + fmaf(a3.z, w[14], a3.w * w[15]);
        Cv[k8] = (d0 + d1) + (d2 + d3);
    }
    float s = Cv[0];
#pragma unroll
    for (int k8 = 1; k8 < 8; ++k8) s = fmaxf(s, Cv[k8]);
    s = fmaxf(s, __shfl_xor_sync(0xffffffffu, s, 16));   // combine halves
    float r = __fdividef(1.0f, s);
#pragma unroll
    for (int k8 = 0; k8 < 8; ++k8)
        dstM[pidx * 256 + (h * 8 + k8) * 16 + c] = Cv[k8] * r;
    if (lane < 16) dstLam[pidx * 16 + c] = lamP + mA + __logf(s);
}

// Dynamic smem layout (floats):
//   ring  at 0      : [2][8][D][48]            = 6144
//   stage at 6144   : [4][2][4][RSTRIDE]        = 9344   (producer row staging)
//   post aliases (after streaming): m1[4][16][17], lam1[4][16], X[8*256], lamX[8*16]
#define OFF_RING  0
#define OFF_STAGE 6144
#define DYN_FLOATS (6144 + 4 * 2 * 4 * RSTRIDE)
#define DYN_BYTES  (DYN_FLOATS * 4)
#define OFF_M1    0
#define OFF_LAM1  (4 * 16 * 17)
#define OFF_X     (OFF_LAM1 + 64)
#define OFF_LAMX  (OFF_X + 8 * 256)

// ===========================================================================
// Warp-specialized fused kernel with coalesced full-row alogp staging.
// 256 threads: warps 0-3 consume (recurrence, smem-only), warps 4-7 produce:
//   cp.async the FULL 1152B alogp row (every byte requested -> DRAM-efficient),
//   pick row[c*18+a] from smem, build e-vectors into the double-buffered ring.
// ===========================================================================
__global__ __launch_bounds__(256, 3) void hmm_fused(
    const float* __restrict__ alogp,
    const float* __restrict__ stopl,
    const float* __restrict__ startl,
    const int* __restrict__ actions,
    const int* __restrict__ lengths,
    float* __restrict__ out)
{
    extern __shared__ __align__(16) float dyn[];
    float* ring  = dyn + OFF_RING;
    float* stage = dyn + OFF_STAGE;

    const int wib  = threadIdx.x >> 5;
    const int lane = threadIdx.x & 31;
    const int b    = blockIdx.x >> 4;             // 64 batches
    const int blk  = blockIdx.x & 15;             // 16 blocks per batch
    const int pw   = wib & 3;                     // role-local warp id 0..3
    const int pr   = blk * 4 + pw;                // chunk-pair id within batch
    const int sub  = lane >> 4;
    const int c    = lane & 15;
    const int ch   = pr * 2 + sub;                // 128 chunks per batch
    const int i0   = 1 + ch * CL;

    __shared__ int s_act[4][2 * CL];
    __shared__ __align__(16) float bm[6 * 256];
    __shared__ float lamB[6 * 16];
    __shared__ __align__(16) float sw[4][16];
    __shared__ int s_last, s_last2;

    const int len = lengths[b];
    int nact = max(0, min(len - i0, min(CL, MAXT - i0)));

    float p[HB];
#pragma unroll
    for (int k = 0; k < HB; ++k) p[k] = (k == c) ? 1.0f : 0.0f;
    float lam = 0.0f;

    const unsigned idx16_0 = ((unsigned)b * T1 + (unsigned)i0) * 16u + (unsigned)c;
    const float2* stop2 = (const float2*)stopl;

    // producer-only scalars (both subs)
    const int i0A = 1 + (pr * 2) * CL;
    const int nactA = max(0, min(len - i0A, min(CL, MAXT - i0A)));
    const int nactB = max(0, min(len - (i0A + CL), min(CL, MAXT - (i0A + CL))));
    const size_t rowbaseA = ((size_t)b * T1 + (size_t)i0A) * NA * HB;   // floats
    const size_t rowbaseB = rowbaseA + (size_t)CL * NA * HB;
    unsigned stage_u32 = (unsigned)__cvta_generic_to_shared(stage);

    if (wib >= 4) {
        // actions for the pair region into s_act[pw]
        int totA = min(2 * CL, MAXT - i0A);
        for (int idx = lane; idx < totA; idx += 32)
            s_act[pw][idx] = actions[(size_t)b * MAXT + i0A + idx];
        __syncwarp();
    }

    // ---- streaming pipeline: PH fill phases, PH eat phases, offset by 1 ----
    for (int ph = 0; ph <= PH; ++ph) {
        if (wib >= 4 && ph < PH) {
            // PRODUCER
            const int t0 = ph * D;
            // per-lane stop/start for my sub's chunk (coalesced rows)
            float2 s2[D]; float st[D];
            const int mynact = sub ? nactB : nactA;
#pragma unroll
            for (int u = 0; u < D; ++u) {
                int t = t0 + u;
                if (t < mynact) {
                    unsigned idx = idx16_0 + (unsigned)t * 16u;
                    s2[u] = __ldg(stop2 + idx);
                    st[u] = __ldg(startl + idx);
                }
            }
            // row staging: 4 groups of (2 steps x 2 subs) = 4 rows, double-buffered
            // issue group 0
            {
                const int tA = t0;
#pragma unroll
                for (int r = 0; r < 4; ++r) {
                    int u = r >> 1, sb = r & 1;
                    int t = tA + u;
                    int na = sb ? nactB : nactA;
                    if (t < na) {
                        const float* srow = alogp + (sb ? rowbaseB : rowbaseA) + (size_t)t * (NA * HB);
                        unsigned drow = stage_u32 + (unsigned)(((pw * 2 + 0) * 4 + r) * RSTRIDE) * 4u;
                        CP_ASYNC16(drow + lane * 16u, srow + lane * 4);
                        CP_ASYNC16(drow + (lane + 32) * 16u, srow + (lane + 32) * 4);
                        if (lane < 8)
                            CP_ASYNC16(drow + (lane + 64) * 16u, srow + (lane + 64) * 4);
                    }
                }
                CP_COMMIT();
            }
#pragma unroll
            for (int g = 0; g < 4; ++g) {
                if (g < 3) {
                    const int tA = t0 + (g + 1) * 2;
#pragma unroll
                    for (int r = 0; r < 4; ++r) {
                        int u = r >> 1, sb = r & 1;
                        int t = tA + u;
                        int na = sb ? nactB : nactA;
                        if (t < na) {
                            const float* srow = alogp + (sb ? rowbaseB : rowbaseA) + (size_t)t * (NA * HB);
                            unsigned drow = stage_u32 + (unsigned)(((pw * 2 + ((g + 1) & 1)) * 4 + r) * RSTRIDE) * 4u;
                            CP_ASYNC16(drow + lane * 16u, srow + lane * 4);
                            CP_ASYNC16(drow + (lane + 32) * 16u, srow + (lane + 32) * 4);
                            if (lane < 8)
                                CP_ASYNC16(drow + (lane + 64) * 16u, srow + (lane + 64) * 4);
                        }
                    }
                    CP_COMMIT();
                    CP_WAIT(1);
                } else {
                    CP_WAIT(0);
                }
                __syncwarp();
                // consume group g: 2 steps, my sub's rows
#pragma unroll
                for (int u = 0; u < 2; ++u) {
                    int lstep = g * 2 + u;           // 0..7 within phase
                    int t = t0 + lstep;
                    if (t < mynact) {
                        int a = s_act[pw][sub * CL + t];
                        const float* row = stage + ((pw * 2 + (g & 1)) * 4 + u * 2 + sub) * RSTRIDE;
                        float al = row[c * NA + a];
                        float* vb = ring + (((ph & 1) * 8 + (pw * 2 + sub)) * D + lstep) * 48;
                        vb[c]      = __expf(s2[lstep].x);
                        vb[16 + c] = __expf(al + st[lstep]);
                        vb[32 + c] = __expf(al + s2[lstep].y);
                    }
                }
                __syncwarp();   // protect stage buffer reuse across the warp
            }
        }
        if (wib < 4 && ph > 0) {
            // CONSUMER: recurrence over D steps of the previous phase.
            const int t0 = (ph - 1) * D;
            const float* rb = ring + ((((ph - 1) & 1) * 8 + (wib * 2 + sub)) * D) * 48;
#pragma unroll
            for (int u = 0; u < D; ++u) {
                int t = t0 + u;
                if (t >= nact) break;          // uniform within each half-warp
                const float4* E = (const float4*)(rb + u * 48);
                float4 e0 = E[0], e1 = E[1], e2 = E[2],  e3 = E[3];
                float t0d = fmaf(e0.x, p[0],  e0.y * p[1])  + fmaf(e0.z, p[2],  e0.w * p[3]);
                float t1d = fmaf(e1.x, p[4],  e1.y * p[5])  + fmaf(e1.z, p[6],  e1.w * p[7]);
                float t2d = fmaf(e2.x, p[8],  e2.y * p[9])  + fmaf(e2.z, p[10], e2.w * p[11]);
                float t3d = fmaf(e3.x, p[12], e3.y * p[13]) + fmaf(e3.z, p[14], e3.w * p[15]);
                float s = (t0d + t1d) + (t2d + t3d);
                float4 a0 = E[4], a1 = E[5], a2 = E[6],  a3 = E[7];
                float4 o0 = E[8], o1 = E[9], o2 = E[10], o3 = E[11];
                p[0]  = fmaf(o0.x, p[0],  a0.x * s);
                p[1]  = fmaf(o0.y, p[1],  a0.y * s);
                p[2]  = fmaf(o0.z, p[2],  a0.z * s);
                p[3]  = fmaf(o0.w, p[3],  a0.w * s);
                p[4]  = fmaf(o1.x, p[4],  a1.x * s);
                p[5]  = fmaf(o1.y, p[5],  a1.y * s);
                p[6]  = fmaf(o1.z, p[6],  a1.z * s);
                p[7]  = fmaf(o1.w, p[7],  a1.w * s);
                p[8]  = fmaf(o2.x, p[8],  a2.x * s);
                p[9]  = fmaf(o2.y, p[9],  a2.y * s);
                p[10] = fmaf(o2.z, p[10], a2.z * s);
                p[11] = fmaf(o2.w, p[11], a2.w * s);
                p[12] = fmaf(o3.x, p[12], a3.x * s);
                p[13] = fmaf(o3.y, p[13], a3.y * s);
                p[14] = fmaf(o3.z, p[14], a3.z * s);
                p[15] = fmaf(o3.w, p[15], a3.w * s);
                if ((t & 3) == 3) {            // renorm every 4 steps
                    float r = __fdividef(1.0f, s);
                    lam += __logf(s);
#pragma unroll
                    for (int k = 0; k < HB; ++k) p[k] *= r;
                }
            }
        }
        __syncthreads();
    }

    // ---- post-stream aliases over dynamic smem ----
    float* m1p   = dyn + OFF_M1;     // [4][16][17]
    float* lam1p = dyn + OFF_LAM1;   // [4][16]
    float* X     = dyn + OFF_X;      // [8*256]
    float* lamX  = dyn + OFF_LAMX;   // [8*16]

    // ---- warp fold (consumer warps): R_true = M1_true * M0_true ----
    if (wib < 4) {
        if (sub == 1) {
#pragma unroll
            for (int k = 0; k < HB; ++k) m1p[(wib * 16 + c) * 17 + k] = p[k];
            lam1p[wib * 16 + c] = lam;
        }
        __syncwarp();
        if (sub == 0) {
            float m1 = lam1p[wib * 16 + 0];
#pragma unroll
            for (int j = 1; j < HB; ++j) m1 = fmaxf(m1, lam1p[wib * 16 + j]);
            float R[HB];
#pragma unroll
            for (int k = 0; k < HB; ++k) R[k] = 0.0f;
#pragma unroll
            for (int j = 0; j < HB; ++j) {
                float wj = p[j] * __expf(lam1p[wib * 16 + j] - m1);
                const float* Aj = m1p + (wib * 16 + j) * 17;
#pragma unroll
                for (int k = 0; k < HB; ++k) R[k] = fmaf(wj, Aj[k], R[k]);
            }
            float s = R[0];
#pragma unroll
            for (int k = 1; k < HB; ++k) s = fmaxf(s, R[k]);
            float r = __fdividef(1.0f, s);
#pragma unroll
            for (int k = 0; k < HB; ++k)
                bm[wib * 256 + k * 16 + c] = R[k] * r;
            lamB[wib * 16 + c] = lam + m1 + __logf(s);
        }
    }
    __syncthreads();

    // ---- block fold: 4 warp-mats -> 1 block-mat -> gmem ----
    if (wib < 2)
        mat_product2(bm, lamB, bm + 4 * 256, lamB + 4 * 16, wib, lane, sw[wib], false);
    __syncthreads();
    if (wib == 0)
        mat_product2(bm + 4 * 256, lamB + 4 * 16,
                     g_mats + (size_t)(b * NMB + blk) * 256,
                     g_lam  + (size_t)(b * NMB + blk) * 16,
                     0, lane, sw[0], false);

    // ---- last-block election ----
    __threadfence();
    __syncthreads();
    if (threadIdx.x == 0) {
        int old = atomicAdd(&g_cnt[b], 1);
        s_last = (old == BPB - 1);
        if (old == BPB - 1) g_cnt[b] = 0;
    }
    __syncthreads();
    if (!s_last) return;

    // ---- tree combine over 16 block-mats (consumer warps work) ----
    float* Y = bm; float* lamY = lamB;
    const float* gM = g_mats + (size_t)b * NMB * 256;
    const float* gL = g_lam  + (size_t)b * NMB * 16;

    if (wib < 4) {
        mat_product2(gM, gL, X, lamX, wib,     lane, sw[wib], true);
        mat_product2(gM, gL, X, lamX, wib + 4, lane, sw[wib], true);
    }
    __syncthreads();
    if (wib < 4) mat_product2(X, lamX, Y, lamY, wib, lane, sw[wib], false);
    __syncthreads();
    if (wib < 2) mat_product2(Y, lamY, X, lamX, wib, lane, sw[wib], false);
    __syncthreads();
    if (wib == 0) mat_product2(X, lamX, Y, lamY, 0, lane, sw[0], false);
    __syncthreads();

    if (wib == 0) {
        const size_t rb = (size_t)b * T1;
        const int a0i = actions[(size_t)b * MAXT];

        float f0 = startl[rb * 16 + c] + alogp[(rb * 16 + (size_t)c) * 18 + a0i];
        float t = lamY[c] + f0;
        float F0 = t;
        F0 = fmaxf(F0, __shfl_xor_sync(0xffffffffu, F0, 1));
        F0 = fmaxf(F0, __shfl_xor_sync(0xffffffffu, F0, 2));
        F0 = fmaxf(F0, __shfl_xor_sync(0xffffffffu, F0, 4));
        F0 = fmaxf(F0, __shfl_xor_sync(0xffffffffu, F0, 8));
        if (lane < 16) sw[0][c] = __expf(t - F0);
        __syncwarp();
        const float4* M4 = (const float4*)Y;
        const float4* W4 = (const float4*)sw[0];
        float4 m0 = M4[c * 4 + 0], m1 = M4[c * 4 + 1];
        float4 m2 = M4[c * 4 + 2], m3 = M4[c * 4 + 3];
        float4 w0 = W4[0], w1 = W4[1], w2 = W4[2], w3 = W4[3];
        float d0 = fmaf(m0.x, w0.x, m0.y * w0.y) + fmaf(m0.z, w0.z, m0.w * w0.w);
        float d1 = fmaf(m1.x, w1.x, m1.y * w1.y) + fmaf(m1.z, w1.z, m1.w * w1.w);
        float d2 = fmaf(m2.x, w2.x, m2.y * w2.y) + fmaf(m2.z, w2.z, m2.w * w2.w);
        float d3 = fmaf(m3.x, w3.x, m3.y * w3.y) + fmaf(m3.z, w3.z, m3.w * w3.w);
        float v = (d0 + d1) + (d2 + d3);

        float u = stopl[((rb + (size_t)len) * 16 + (size_t)c) * 2];
        float mS = u;
        mS = fmaxf(mS, __shfl_xor_sync(0xffffffffu, mS, 1));
        mS = fmaxf(mS, __shfl_xor_sync(0xffffffffu, mS, 2));
        mS = fmaxf(mS, __shfl_xor_sync(0xffffffffu, mS, 4));
        mS = fmaxf(mS, __shfl_xor_sync(0xffffffffu, mS, 8));
        float term = __expf(u - mS) * v;
        term += __shfl_xor_sync(0xffffffffu, term, 1);
        term += __shfl_xor_sync(0xffffffffu, term, 2);
        term += __shfl_xor_sync(0xffffffffu, term, 4);
        term += __shfl_xor_sync(0xffffffffu, term, 8);

        if (lane == 0) {
            g_partial[b] = -(F0 + mS + __logf(term));
            __threadfence();
            int old2 = atomicAdd(&g_cnt2, 1);
            s_last2 = (old2 == NB - 1);
            if (old2 == NB - 1) g_cnt2 = 0;
        }
    }
    __syncthreads();

    if (s_last2 && wib == 0) {
        float v = ldcg(&g_partial[lane]) + ldcg(&g_partial[lane + 32]);
        v += __shfl_xor_sync(0xffffffffu, v, 1);
        v += __shfl_xor_sync(0xffffffffu, v, 2);
        v += __shfl_xor_sync(0xffffffffu, v, 4);
        v += __shfl_xor_sync(0xffffffffu, v, 8);
        v += __shfl_xor_sync(0xffffffffu, v, 16);
        if (lane == 0) *out = v;
    }
}

extern "C" void kernel_launch(void* const* d_in, const int* in_sizes, int n_in,
                              void* d_out, int out_size)
{
    const float* alogp   = (const float*)d_in[0];
    const float* stopl   = (const float*)d_in[1];
    const float* startl  = (const float*)d_in[2];
    const int*   actions = (const int*)d_in[3];
    const int*   lengths = (const int*)d_in[4];
    float* out = (float*)d_out;

    cudaFuncSetAttribute(hmm_fused,
                         cudaFuncAttributeMaxDynamicSharedMemorySize, DYN_BYTES);
    hmm_fused<<<NB * BPB, 256, DYN_BYTES>>>(alogp, stopl, startl, actions, lengths, out);
}

// round 14
// speedup vs baseline: 1.1084x; 1.1084x over previous
#include <cuda_runtime.h>

// Problem constants (fixed by the dataset)
#define NB   64          // batch
#define T1   4097        // maxT+1
#define MAXT 4096
#define HB   16          // hidden states
#define NA   18          // actions
#define CL   64          // chunk length (steps per chunk)
#define NPR  32          // chunk-pairs per batch (each warp folds 2 chunks -> 1 matrix)

// Scratch: per (batch, pair) folded transfer matrix, column c scaled by exp(lam[c]).
__device__ float g_mats[NB * NPR * HB * HB];   // 2 MB
__device__ float g_lam[NB * NPR * HB];

// Prefetch bank: 8 steps of (stop.xy, start, action_logp) per lane.
struct PFB { float2 s[8]; float t[8]; float a[8]; };

__device__ __forceinline__ void load_group(
    int g0, int nact, unsigned idx16_0,
    const float2* __restrict__ stop2, const float* __restrict__ startl,
    const float* __restrict__ alogp, const int* __restrict__ sa,
    PFB& B)
{
#pragma unroll
    for (int u = 0; u < 8; ++u) {
        int t = g0 + u;
        if (t < nact) {
            unsigned idx = idx16_0 + (unsigned)t * 16u;
            B.s[u] = __ldg(stop2 + idx);                         // (beta, omb)
            B.t[u] = __ldg(startl + idx);                        // start
            B.a[u] = __ldg(alogp + idx * 18u + (unsigned)sa[t]); // action logp
        } else {
            B.s[u] = make_float2(0.f, 0.f); B.t[u] = 0.f; B.a[u] = 0.f;
        }
    }
}

// Per step i (exact linear map):
//   s     = sum_j exp(beta_j) * p[j]
//   p[k] <- exp(al_k+start_k)*s + exp(al_k+omb_k)*p[k]
// Every 4 steps: p /= s, lam += log(s)  (conditioning; p*e^lam invariant;
// between renorms values stay fp32-safe; entries that flush are >=87 nats
// below the column max -> logsumexp-negligible).
__device__ __forceinline__ void consume_group(
    int g0, int nsteps, int nact, int c, float* __restrict__ vb2,
    PFB& B, float (&p)[HB], float& lam)
{
#pragma unroll
    for (int u = 0; u < 8; ++u) {
        int t = g0 + u;
        if (t >= nsteps) return;   // nsteps is warp-uniform
        float eb   = __expf(B.s[u].x);
        float easv = __expf(B.a[u] + B.t[u]);
        float eaov = __expf(B.a[u] + B.s[u].y);
        float* vb = vb2 + (u & 1) * 48;
        vb[c]      = eb;
        vb[16 + c] = easv;
        vb[32 + c] = eaov;
        __syncwarp();
        const float4* EB = (const float4*)vb;
        float4 e0 = EB[0], e1 = EB[1], e2 = EB[2], e3 = EB[3];
        float t0 = fmaf(e0.x, p[0],  e0.y * p[1])  + fmaf(e0.z, p[2],  e0.w * p[3]);
        float t1 = fmaf(e1.x, p[4],  e1.y * p[5])  + fmaf(e1.z, p[6],  e1.w * p[7]);
        float t2 = fmaf(e2.x, p[8],  e2.y * p[9])  + fmaf(e2.z, p[10], e2.w * p[11]);
        float t3 = fmaf(e3.x, p[12], e3.y * p[13]) + fmaf(e3.z, p[14], e3.w * p[15]);
        float s = (t0 + t1) + (t2 + t3);
        if (t < nact) {            // uniform within each half-warp
            const float4* EA = (const float4*)(vb + 16);
            const float4* EO = (const float4*)(vb + 32);
            float4 a0 = EA[0], a1 = EA[1], a2 = EA[2], a3 = EA[3];
            float4 o0 = EO[0], o1 = EO[1], o2 = EO[2], o3 = EO[3];
            p[0]  = fmaf(o0.x, p[0],  a0.x * s);
            p[1]  = fmaf(o0.y, p[1],  a0.y * s);
            p[2]  = fmaf(o0.z, p[2],  a0.z * s);
            p[3]  = fmaf(o0.w, p[3],  a0.w * s);
            p[4]  = fmaf(o1.x, p[4],  a1.x * s);
            p[5]  = fmaf(o1.y, p[5],  a1.y * s);
            p[6]  = fmaf(o1.z, p[6],  a1.z * s);
            p[7]  = fmaf(o1.w, p[7],  a1.w * s);
            p[8]  = fmaf(o2.x, p[8],  a2.x * s);
            p[9]  = fmaf(o2.y, p[9],  a2.y * s);
            p[10] = fmaf(o2.z, p[10], a2.z * s);
            p[11] = fmaf(o2.w, p[11], a2.w * s);
            p[12] = fmaf(o3.x, p[12], a3.x * s);
            p[13] = fmaf(o3.y, p[13], a3.y * s);
            p[14] = fmaf(o3.z, p[14], a3.z * s);
            p[15] = fmaf(o3.w, p[15], a3.w * s);
            if ((t & 3) == 3) {
                float r = __fdividef(1.0f, s);
                lam += __logf(s);
#pragma unroll
                for (int k = 0; k < HB; ++k) p[k] *= r;
            }
        }
    }
}

// One warp handles TWO adjacent chunks (lanes 0-15 = earlier, 16-31 = later)
// and folds them into ONE transfer matrix at the end.
__global__ __launch_bounds__(128) void hmm_chunk_kernel(
    const float* __restrict__ alogp,
    const float* __restrict__ stopl,
    const float* __restrict__ startl,
    const int* __restrict__ actions,
    const int* __restrict__ lengths,
    float* __restrict__ out)
{
    if (blockIdx.x == 0 && threadIdx.x == 0) *out = 0.0f;

    const int wib  = threadIdx.x >> 5;
    const int lane = threadIdx.x & 31;
    const int gw   = blockIdx.x * 4 + wib;     // 0..2047
    const int b    = gw >> 5;                  // 64 batches
    const int pr   = gw & 31;                  // 32 chunk-pairs
    const int sub  = lane >> 4;
    const int c    = lane & 15;
    const int ch   = pr * 2 + sub;
    const int i0   = 1 + ch * CL;

    __shared__ int s_act[4][2 * CL];
    __shared__ __align__(16) float s_vec[4][2][2][3 * HB];
    __shared__ __align__(16) float s_m1[4][HB][HB + 1];
    __shared__ float s_lam1[4][HB];

    const int len = lengths[b];

    int cnt  = min(CL, MAXT - i0);
    int nact = max(0, min(len - i0, cnt));
    const int i0p  = 1 + pr * 2 * CL;
    int n0 = max(0, min(len - i0p, min(CL, MAXT - i0p)));
    int n1 = max(0, min(len - (i0p + CL), min(CL, MAXT - (i0p + CL))));
    int nsteps = max(n0, n1);

    int totA = min(2 * CL, MAXT - i0p);
    for (int idx = lane; idx < totA; idx += 32)
        s_act[wib][idx] = actions[(size_t)b * MAXT + i0p + idx];
    __syncwarp();

    float p[HB];
#pragma unroll
    for (int k = 0; k < HB; ++k) p[k] = (k == c) ? 1.0f : 0.0f;
    float lam = 0.0f;

    if (nsteps > 0) {
        const unsigned idx16_0 = ((unsigned)b * T1 + (unsigned)i0) * 16u + (unsigned)c;
        const float2* stop2 = (const float2*)stopl;
        const int* sa = &s_act[wib][sub * CL];
        float* vb2 = &s_vec[wib][sub][0][0];

        PFB B0, B1;
        load_group(0, nact, idx16_0, stop2, startl, alogp, sa, B0);
        for (int g0 = 0; g0 < nsteps; g0 += 16) {
            load_group(g0 + 8, nact, idx16_0, stop2, startl, alogp, sa, B1);
            consume_group(g0, nsteps, nact, c, vb2, B0, p, lam);
            if (g0 + 8 < nsteps) {
                load_group(g0 + 16, nact, idx16_0, stop2, startl, alogp, sa, B0);
                consume_group(g0 + 8, nsteps, nact, c, vb2, B1, p, lam);
            }
        }
    }

    // Fold: R_true = M1_true * M0_true.
    // Column c: R[:,c] = e^{lam0_c} * sum_j M0hat[j][c] e^{lam1_j} M1hat[:,j]
    __syncwarp();
    if (sub == 1) {
#pragma unroll
        for (int k = 0; k < HB; ++k) s_m1[wib][c][k] = p[k];   // row c = column c of M1hat
        s_lam1[wib][c] = lam;
    }
    __syncwarp();
    if (sub == 0) {
        float m1 = s_lam1[wib][0];
#pragma unroll
        for (int j = 1; j < HB; ++j) m1 = fmaxf(m1, s_lam1[wib][j]);
        float R[HB];
#pragma unroll
        for (int k = 0; k < HB; ++k) R[k] = 0.0f;
#pragma unroll
        for (int j = 0; j < HB; ++j) {
            float wj = p[j] * __expf(s_lam1[wib][j] - m1);
            const float* Aj = &s_m1[wib][j][0];
#pragma unroll
            for (int k = 0; k < HB; ++k) R[k] = fmaf(wj, Aj[k], R[k]);
        }
        float s = R[0];
#pragma unroll
        for (int k = 1; k < HB; ++k) s = fmaxf(s, R[k]);
        float r = __fdividef(1.0f, s);
        size_t mb = (size_t)(b * NPR + pr) * (HB * HB);
#pragma unroll
        for (int k = 0; k < HB; ++k)
            g_mats[mb + (size_t)k * HB + c] = R[k] * r;
        g_lam[(size_t)(b * NPR + pr) * HB + c] = lam + m1 + __logf(s);
    }
}

// ---------------------------------------------------------------------------
// Tree combine: one block (8 warps, 256 thr) per batch; one warp per product.
// Halves split the 16 output rows -> spill-free (~40 live regs).
//   C[:,c] = sum_j A[:,j] * (e^{lamA_j - mA} * P[j][c]);  renorm by column max.
// ---------------------------------------------------------------------------
__device__ __forceinline__ void mat_product2(
    const float* __restrict__ srcM, const float* __restrict__ srcLam,
    float* __restrict__ dstM, float* __restrict__ dstLam,
    int pidx, int lane, float* __restrict__ sw /* 16-float per-warp scratch */)
{
    const int c = lane & 15;
    const int h = lane >> 4;                    // rows [8h, 8h+8)
    const float* Pm = srcM + (size_t)(2 * pidx) * 256;
    const float* Am = srcM + (size_t)(2 * pidx + 1) * 256;
    float lamP = srcLam[(2 * pidx) * 16 + c];
    float lamA = srcLam[(2 * pidx + 1) * 16 + c];
    float mA = lamA;
    mA = fmaxf(mA, __shfl_xor_sync(0xffffffffu, mA, 1));
    mA = fmaxf(mA, __shfl_xor_sync(0xffffffffu, mA, 2));
    mA = fmaxf(mA, __shfl_xor_sync(0xffffffffu, mA, 4));
    mA = fmaxf(mA, __shfl_xor_sync(0xffffffffu, mA, 8));
    if (lane < 16) sw[c] = __expf(lamA - mA);
    __syncwarp();
    float w[16];
#pragma unroll
    for (int j = 0; j < 16; ++j) w[j] = sw[j] * Pm[j * 16 + c];
    __syncwarp();
    float Cv[8];
#pragma unroll
    for (int k8 = 0; k8 < 8; ++k8) {
        const float4* A4 = (const float4*)(Am + (h * 8 + k8) * 16);
        float4 a0 = A4[0], a1 = A4[1], a2 = A4[2], a3 = A4[3];
        float d0 = fmaf(a0.x, w[0],  a0.y * w[1])  + fmaf(a0.z, w[2],  a0.w * w[3]);
        float d1 = fmaf(a1.x, w[4],  a1.y * w[5])  + fmaf(a1.z, w[6],  a1.w * w[7]);
        float d2 = fmaf(a2.x, w[8],  a2.y * w[9])  + fmaf(a2.z, w[10], a2.w * w[11]);
        float d3 = fmaf(a3.x, w[12], a3.y * w[13]) + fmaf(a3.z, w[14], a3.w * w[15]);
        Cv[k8] = (d0 + d1) + (d2 + d3);
    }
    float s = Cv[0];
#pragma unroll
    for (int k8 = 1; k8 < 8; ++k8) s = fmaxf(s, Cv[k8]);
    s = fmaxf(s, __shfl_xor_sync(0xffffffffu, s, 16));   // combine halves
    float r = __fdividef(1.0f, s);
#pragma unroll
    for (int k8 = 0; k8 < 8; ++k8)
        dstM[pidx * 256 + (h * 8 + k8) * 16 + c] = Cv[k8] * r;
    if (lane < 16) dstLam[pidx * 16 + c] = lamP + mA + __logf(s);
}

__global__ __launch_bounds__(256, 1) void hmm_combine_tree(
    const float* __restrict__ alogp,
    const float* __restrict__ stopl,
    const float* __restrict__ startl,
    const int* __restrict__ actions,
    const int* __restrict__ lengths,
    float* __restrict__ out)
{
    __shared__ __align__(16) float bufA[16 * 256];
    __shared__ __align__(16) float bufB[8 * 256];
    __shared__ float lamA[16 * 16];
    __shared__ float lamB[8 * 16];
    __shared__ __align__(16) float sw[8][16];

    const int b    = blockIdx.x;
    const int warp = threadIdx.x >> 5;
    const int lane = threadIdx.x & 31;

    const float* gM = g_mats + (size_t)b * NPR * 256;
    const float* gL = g_lam  + (size_t)b * NPR * 16;

    // L1: 32 -> 16 (gmem -> bufA); each warp does 2 products
    mat_product2(gM, gL, bufA, lamA, warp,     lane, sw[warp]);
    mat_product2(gM, gL, bufA, lamA, warp + 8, lane, sw[warp]);
    __syncthreads();
    // L2: 16 -> 8
    mat_product2(bufA, lamA, bufB, lamB, warp, lane, sw[warp]);
    __syncthreads();
    // L3: 8 -> 4
    if (warp < 4) mat_product2(bufB, lamB, bufA, lamA, warp, lane, sw[warp]);
    __syncthreads();
    // L4: 4 -> 2
    if (warp < 2) mat_product2(bufA, lamA, bufB, lamB, warp, lane, sw[warp]);
    __syncthreads();
    // L5: 2 -> 1  (final in bufA[0], lam in lamA[0..15])
    if (warp == 0) mat_product2(bufB, lamB, bufA, lamA, 0, lane, sw[0]);
    __syncthreads();

    if (warp == 0) {
        const int c = lane & 15;
        const int len = lengths[b];
        const size_t rb = (size_t)b * T1;
        const int a0i = actions[(size_t)b * MAXT];

        float f0 = startl[rb * 16 + c] + alogp[(rb * 16 + (size_t)c) * 18 + a0i];
        float t = lamA[c] + f0;
        float F0 = t;
        F0 = fmaxf(F0, __shfl_xor_sync(0xffffffffu, F0, 1));
        F0 = fmaxf(F0, __shfl_xor_sync(0xffffffffu, F0, 2));
        F0 = fmaxf(F0, __shfl_xor_sync(0xffffffffu, F0, 4));
        F0 = fmaxf(F0, __shfl_xor_sync(0xffffffffu, F0, 8));
        if (lane < 16) sw[0][c] = __expf(t - F0);
        __syncwarp();
        const float4* M4 = (const float4*)bufA;
        const float4* W4 = (const float4*)sw[0];
        float4 m0 = M4[c * 4 + 0], m1 = M4[c * 4 + 1];
        float4 m2 = M4[c * 4 + 2], m3 = M4[c * 4 + 3];
        float4 w0 = W4[0], w1 = W4[1], w2 = W4[2], w3 = W4[3];
        float d0 = fmaf(m0.x, w0.x, m0.y * w0.y) + fmaf(m0.z, w0.z, m0.w * w0.w);
        float d1 = fmaf(m1.x, w1.x, m1.y * w1.y) + fmaf(m1.z, w1.z, m1.w * w1.w);
        float d2 = fmaf(m2.x, w2.x, m2.y * w2.y) + fmaf(m2.z, w2.z, m2.w * w2.w);
        float d3 = fmaf(m3.x, w3.x, m3.y * w3.y) + fmaf(m3.z, w3.z, m3.w * w3.w);
        float v = (d0 + d1) + (d2 + d3);      // lane c: (M w)_c

        float u = stopl[((rb + (size_t)len) * 16 + (size_t)c) * 2];
        float mS = u;
        mS = fmaxf(mS, __shfl_xor_sync(0xffffffffu, mS, 1));
        mS = fmaxf(mS, __shfl_xor_sync(0xffffffffu, mS, 2));
        mS = fmaxf(mS, __shfl_xor_sync(0xffffffffu, mS, 4));
        mS = fmaxf(mS, __shfl_xor_sync(0xffffffffu, mS, 8));
        float term = __expf(u - mS) * v;
        term += __shfl_xor_sync(0xffffffffu, term, 1);
        term += __shfl_xor_sync(0xffffffffu, term, 2);
        term += __shfl_xor_sync(0xffffffffu, term, 4);
        term += __shfl_xor_sync(0xffffffffu, term, 8);
        if (lane == 0) atomicAdd(out, -(F0 + mS + __logf(term)));
    }
}

extern "C" void kernel_launch(void* const* d_in, const int* in_sizes, int n_in,
                              void* d_out, int out_size)
{
    const float* alogp   = (const float*)d_in[0];
    const float* stopl   = (const float*)d_in[1];
    const float* startl  = (const float*)d_in[2];
    const int*   actions = (const int*)d_in[3];
    const int*   lengths = (const int*)d_in[4];
    float* out = (float*)d_out;

    hmm_chunk_kernel<<<(NB * NPR) / 4, 128>>>(alogp, stopl, startl, actions, lengths, out);
    hmm_combine_tree<<<NB, 256>>>(alogp, stopl, startl, actions, lengths, out);
}

// round 15
// speedup vs baseline: 1.1168x; 1.0075x over previous
#include <cuda_runtime.h>

// Problem constants (fixed by the dataset)
#define NB   64          // batch
#define T1   4097        // maxT+1
#define MAXT 4096
#define HB   16          // hidden states
#define NA   18          // actions
#define CL   64          // chunk length (steps per chunk)
#define NPR  32          // chunk-pairs per batch (each warp folds 2 chunks -> 1 matrix)

// Scratch: per (batch, pair) folded transfer matrix, column c scaled by exp(lam[c]).
__device__ float g_mats[NB * NPR * HB * HB];   // 2 MB
__device__ float g_lam[NB * NPR * HB];

#define CP_ASYNC16(dst, src) \
    asm volatile("cp.async.cg.shared.global [%0], [%1], 16;" :: "r"(dst), "l"(src))
#define CP_COMMIT() asm volatile("cp.async.commit_group;" ::: "memory")
#define CP_WAIT0()  asm volatile("cp.async.wait_group 0;" ::: "memory")

// Prefetch bank: 8 steps of (stop.xy, start, action_logp) per lane.
struct PFB { float2 s[8]; float t[8]; float a[8]; };

__device__ __forceinline__ void load_group(
    int g0, int nact, unsigned idx16_0,
    const float2* __restrict__ stop2, const float* __restrict__ startl,
    const float* __restrict__ alogp, const int* __restrict__ sa,
    PFB& B)
{
#pragma unroll
    for (int u = 0; u < 8; ++u) {
        int t = g0 + u;
        if (t < nact) {
            unsigned idx = idx16_0 + (unsigned)t * 16u;
            B.s[u] = __ldg(stop2 + idx);                         // (beta, omb)
            B.t[u] = __ldg(startl + idx);                        // start
            B.a[u] = __ldg(alogp + idx * 18u + (unsigned)sa[t]); // action logp
        } else {
            B.s[u] = make_float2(0.f, 0.f); B.t[u] = 0.f; B.a[u] = 0.f;
        }
    }
}

// Per step i (exact linear map):
//   s     = sum_j exp(beta_j) * p[j]
//   p[k] <- exp(al_k+start_k)*s + exp(al_k+omb_k)*p[k]
// Every 4 steps: p /= s, lam += log(s)  (conditioning; p*e^lam invariant;
// between renorms values stay fp32-safe; entries that flush are >=87 nats
// below the column max -> logsumexp-negligible).
__device__ __forceinline__ void consume_group(
    int g0, int nsteps, int nact, int c, float* __restrict__ vb2,
    PFB& B, float (&p)[HB], float& lam)
{
#pragma unroll
    for (int u = 0; u < 8; ++u) {
        int t = g0 + u;
        if (t >= nsteps) return;   // nsteps is warp-uniform
        float eb   = __expf(B.s[u].x);
        float easv = __expf(B.a[u] + B.t[u]);
        float eaov = __expf(B.a[u] + B.s[u].y);
        float* vb = vb2 + (u & 1) * 48;
        vb[c]      = eb;
        vb[16 + c] = easv;
        vb[32 + c] = eaov;
        __syncwarp();
        const float4* EB = (const float4*)vb;
        float4 e0 = EB[0], e1 = EB[1], e2 = EB[2], e3 = EB[3];
        float t0 = fmaf(e0.x, p[0],  e0.y * p[1])  + fmaf(e0.z, p[2],  e0.w * p[3]);
        float t1 = fmaf(e1.x, p[4],  e1.y * p[5])  + fmaf(e1.z, p[6],  e1.w * p[7]);
        float t2 = fmaf(e2.x, p[8],  e2.y * p[9])  + fmaf(e2.z, p[10], e2.w * p[11]);
        float t3 = fmaf(e3.x, p[12], e3.y * p[13]) + fmaf(e3.z, p[14], e3.w * p[15]);
        float s = (t0 + t1) + (t2 + t3);
        if (t < nact) {            // uniform within each half-warp
            const float4* EA = (const float4*)(vb + 16);
            const float4* EO = (const float4*)(vb + 32);
            float4 a0 = EA[0], a1 = EA[1], a2 = EA[2], a3 = EA[3];
            float4 o0 = EO[0], o1 = EO[1], o2 = EO[2], o3 = EO[3];
            p[0]  = fmaf(o0.x, p[0],  a0.x * s);
            p[1]  = fmaf(o0.y, p[1],  a0.y * s);
            p[2]  = fmaf(o0.z, p[2],  a0.z * s);
            p[3]  = fmaf(o0.w, p[3],  a0.w * s);
            p[4]  = fmaf(o1.x, p[4],  a1.x * s);
            p[5]  = fmaf(o1.y, p[5],  a1.y * s);
            p[6]  = fmaf(o1.z, p[6],  a1.z * s);
            p[7]  = fmaf(o1.w, p[7],  a1.w * s);
            p[8]  = fmaf(o2.x, p[8],  a2.x * s);
            p[9]  = fmaf(o2.y, p[9],  a2.y * s);
            p[10] = fmaf(o2.z, p[10], a2.z * s);
            p[11] = fmaf(o2.w, p[11], a2.w * s);
            p[12] = fmaf(o3.x, p[12], a3.x * s);
            p[13] = fmaf(o3.y, p[13], a3.y * s);
            p[14] = fmaf(o3.z, p[14], a3.z * s);
            p[15] = fmaf(o3.w, p[15], a3.w * s);
            if ((t & 3) == 3) {
                float r = __fdividef(1.0f, s);
                lam += __logf(s);
#pragma unroll
                for (int k = 0; k < HB; ++k) p[k] *= r;
            }
        }
    }
}

// One warp handles TWO adjacent chunks (lanes 0-15 = earlier, 16-31 = later)
// and folds them into ONE transfer matrix at the end.
__global__ __launch_bounds__(128) void hmm_chunk_kernel(
    const float* __restrict__ alogp,
    const float* __restrict__ stopl,
    const float* __restrict__ startl,
    const int* __restrict__ actions,
    const int* __restrict__ lengths,
    float* __restrict__ out)
{
    if (blockIdx.x == 0 && threadIdx.x == 0) *out = 0.0f;

    const int wib  = threadIdx.x >> 5;
    const int lane = threadIdx.x & 31;
    const int gw   = blockIdx.x * 4 + wib;     // 0..2047
    const int b    = gw >> 5;                  // 64 batches
    const int pr   = gw & 31;                  // 32 chunk-pairs
    const int sub  = lane >> 4;
    const int c    = lane & 15;
    const int ch   = pr * 2 + sub;
    const int i0   = 1 + ch * CL;

    __shared__ int s_act[4][2 * CL];
    __shared__ __align__(16) float s_vec[4][2][2][3 * HB];
    __shared__ __align__(16) float s_m1[4][HB][HB + 1];
    __shared__ float s_lam1[4][HB];

    const int len = lengths[b];

    int cnt  = min(CL, MAXT - i0);
    int nact = max(0, min(len - i0, cnt));
    const int i0p  = 1 + pr * 2 * CL;
    int n0 = max(0, min(len - i0p, min(CL, MAXT - i0p)));
    int n1 = max(0, min(len - (i0p + CL), min(CL, MAXT - (i0p + CL))));
    int nsteps = max(n0, n1);

    int totA = min(2 * CL, MAXT - i0p);
    for (int idx = lane; idx < totA; idx += 32)
        s_act[wib][idx] = actions[(size_t)b * MAXT + i0p + idx];
    __syncwarp();

    float p[HB];
#pragma unroll
    for (int k = 0; k < HB; ++k) p[k] = (k == c) ? 1.0f : 0.0f;
    float lam = 0.0f;

    if (nsteps > 0) {
        const unsigned idx16_0 = ((unsigned)b * T1 + (unsigned)i0) * 16u + (unsigned)c;
        const float2* stop2 = (const float2*)stopl;
        const int* sa = &s_act[wib][sub * CL];
        float* vb2 = &s_vec[wib][sub][0][0];

        PFB B0, B1;
        load_group(0, nact, idx16_0, stop2, startl, alogp, sa, B0);
        for (int g0 = 0; g0 < nsteps; g0 += 16) {
            load_group(g0 + 8, nact, idx16_0, stop2, startl, alogp, sa, B1);
            consume_group(g0, nsteps, nact, c, vb2, B0, p, lam);
            if (g0 + 8 < nsteps) {
                load_group(g0 + 16, nact, idx16_0, stop2, startl, alogp, sa, B0);
                consume_group(g0 + 8, nsteps, nact, c, vb2, B1, p, lam);
            }
        }
    }

    // Fold: R_true = M1_true * M0_true.
    // Column c: R[:,c] = e^{lam0_c} * sum_j M0hat[j][c] e^{lam1_j} M1hat[:,j]
    __syncwarp();
    if (sub == 1) {
#pragma unroll
        for (int k = 0; k < HB; ++k) s_m1[wib][c][k] = p[k];   // row c = column c of M1hat
        s_lam1[wib][c] = lam;
    }
    __syncwarp();
    if (sub == 0) {
        float m1 = s_lam1[wib][0];
#pragma unroll
        for (int j = 1; j < HB; ++j) m1 = fmaxf(m1, s_lam1[wib][j]);
        float R[HB];
#pragma unroll
        for (int k = 0; k < HB; ++k) R[k] = 0.0f;
#pragma unroll
        for (int j = 0; j < HB; ++j) {
            float wj = p[j] * __expf(s_lam1[wib][j] - m1);
            const float* Aj = &s_m1[wib][j][0];
#pragma unroll
            for (int k = 0; k < HB; ++k) R[k] = fmaf(wj, Aj[k], R[k]);
        }
        float s = R[0];
#pragma unroll
        for (int k = 1; k < HB; ++k) s = fmaxf(s, R[k]);
        float r = __fdividef(1.0f, s);
        size_t mb = (size_t)(b * NPR + pr) * (HB * HB);
#pragma unroll
        for (int k = 0; k < HB; ++k)
            g_mats[mb + (size_t)k * HB + c] = R[k] * r;
        g_lam[(size_t)(b * NPR + pr) * HB + c] = lam + m1 + __logf(s);
    }

    // PDL: results are in gmem -> let the dependent (combine) grid launch.
    __threadfence();
    asm volatile("griddepcontrol.launch_dependents;" ::: "memory");
}

// ---------------------------------------------------------------------------
// Tree combine: one block (8 warps, 256 thr) per batch; one warp per product.
// All 5 levels run in smem after a single cp.async staging of the 32 mats.
//   C[:,c] = sum_j A[:,j] * (e^{lamA_j - mA} * P[j][c]);  renorm by column max.
// ---------------------------------------------------------------------------
__device__ __forceinline__ void mat_product2(
    const float* __restrict__ srcM, const float* __restrict__ srcLam,
    float* __restrict__ dstM, float* __restrict__ dstLam,
    int pidx, int lane, float* __restrict__ sw /* 16-float per-warp scratch */)
{
    const int c = lane & 15;
    const int h = lane >> 4;                    // rows [8h, 8h+8)
    const float* Pm = srcM + (size_t)(2 * pidx) * 256;
    const float* Am = srcM + (size_t)(2 * pidx + 1) * 256;
    float lamP = srcLam[(2 * pidx) * 16 + c];
    float lamA = srcLam[(2 * pidx + 1) * 16 + c];
    float mA = lamA;
    mA = fmaxf(mA, __shfl_xor_sync(0xffffffffu, mA, 1));
    mA = fmaxf(mA, __shfl_xor_sync(0xffffffffu, mA, 2));
    mA = fmaxf(mA, __shfl_xor_sync(0xffffffffu, mA, 4));
    mA = fmaxf(mA, __shfl_xor_sync(0xffffffffu, mA, 8));
    if (lane < 16) sw[c] = __expf(lamA - mA);
    __syncwarp();
    float w[16];
#pragma unroll
    for (int j = 0; j < 16; ++j) w[j] = sw[j] * Pm[j * 16 + c];
    __syncwarp();
    float Cv[8];
#pragma unroll
    for (int k8 = 0; k8 < 8; ++k8) {
        const float4* A4 = (const float4*)(Am + (h * 8 + k8) * 16);
        float4 a0 = A4[0], a1 = A4[1], a2 = A4[2], a3 = A4[3];
        float d0 = fmaf(a0.x, w[0],  a0.y * w[1])  + fmaf(a0.z, w[2],  a0.w * w[3]);
        float d1 = fmaf(a1.x, w[4],  a1.y * w[5])  + fmaf(a1.z, w[6],  a1.w * w[7]);
        float d2 = fmaf(a2.x, w[8],  a2.y * w[9])  + fmaf(a2.z, w[10], a2.w * w[11]);
        float d3 = fmaf(a3.x, w[12], a3.y * w[13]) + fmaf(a3.z, w[14], a3.w * w[15]);
        Cv[k8] = (d0 + d1) + (d2 + d3);
    }
    float s = Cv[0];
#pragma unroll
    for (int k8 = 1; k8 < 8; ++k8) s = fmaxf(s, Cv[k8]);
    s = fmaxf(s, __shfl_xor_sync(0xffffffffu, s, 16));   // combine halves
    float r = __fdividef(1.0f, s);
#pragma unroll
    for (int k8 = 0; k8 < 8; ++k8)
        dstM[pidx * 256 + (h * 8 + k8) * 16 + c] = Cv[k8] * r;
    if (lane < 16) dstLam[pidx * 16 + c] = lamP + mA + __logf(s);
}

// dynamic smem: staged mats [32*256] + staged lams [32*16]; the mat area is
// reused as the "B" ping-pong buffer after L1 (staged data dead by then).
#define DYN_FLOATS (32 * 256 + 32 * 16)
#define DYN_BYTES  (DYN_FLOATS * 4)

__global__ __launch_bounds__(256, 1) void hmm_combine_tree(
    const float* __restrict__ alogp,
    const float* __restrict__ stopl,
    const float* __restrict__ startl,
    const int* __restrict__ actions,
    const int* __restrict__ lengths,
    float* __restrict__ out)
{
    extern __shared__ __align__(16) float dyn[];
    __shared__ __align__(16) float bufA[16 * 256];
    __shared__ float lamA[16 * 16];
    __shared__ __align__(16) float sw[8][16];

    const int b    = blockIdx.x;
    const int warp = threadIdx.x >> 5;
    const int lane = threadIdx.x & 31;
    const int tid  = threadIdx.x;

    // With PDL this waits for the chunk grid's results; no-op on plain launch.
    asm volatile("griddepcontrol.wait;" ::: "memory");

    // Stage the 32 matrices + lams into smem (coalesced, one latency shot).
    const float* gM = g_mats + (size_t)b * NPR * 256;
    const float* gL = g_lam  + (size_t)b * NPR * 16;
    unsigned sbase = (unsigned)__cvta_generic_to_shared(dyn);
    for (int i = tid; i < (32 * 256) / 4; i += 256)
        CP_ASYNC16(sbase + (unsigned)i * 16u, ((const float4*)gM) + i);
    for (int i = tid; i < (32 * 16) / 4; i += 256)
        CP_ASYNC16(sbase + (unsigned)(32 * 256 * 4) + (unsigned)i * 16u, ((const float4*)gL) + i);
    CP_COMMIT();
    CP_WAIT0();
    __syncthreads();

    float* sM = dyn;                 // 32 mats (dead after L1 -> reused as bufB)
    float* sL = dyn + 32 * 256;      // 32 lams (dead after L1 -> reused as lamB)
    float* bufB = dyn;               // 8 mats max
    float* lamB = dyn + 32 * 256;    // 8 lams max

    // L1: 32 -> 16 (smem -> bufA); each warp does 2 products
    mat_product2(sM, sL, bufA, lamA, warp,     lane, sw[warp]);
    mat_product2(sM, sL, bufA, lamA, warp + 8, lane, sw[warp]);
    __syncthreads();
    // L2: 16 -> 8 (bufA -> bufB, staged area now dead)
    mat_product2(bufA, lamA, bufB, lamB, warp, lane, sw[warp]);
    __syncthreads();
    // L3: 8 -> 4
    if (warp < 4) mat_product2(bufB, lamB, bufA, lamA, warp, lane, sw[warp]);
    __syncthreads();
    // L4: 4 -> 2
    if (warp < 2) mat_product2(bufA, lamA, bufB, lamB, warp, lane, sw[warp]);
    __syncthreads();
    // L5: 2 -> 1  (final in bufA[0], lam in lamA[0..15])
    if (warp == 0) mat_product2(bufB, lamB, bufA, lamA, 0, lane, sw[0]);
    __syncthreads();

    if (warp == 0) {
        const int c = lane & 15;
        const int len = lengths[b];
        const size_t rb = (size_t)b * T1;
        const int a0i = actions[(size_t)b * MAXT];

        float f0 = startl[rb * 16 + c] + alogp[(rb * 16 + (size_t)c) * 18 + a0i];
        float t = lamA[c] + f0;
        float F0 = t;
        F0 = fmaxf(F0, __shfl_xor_sync(0xffffffffu, F0, 1));
        F0 = fmaxf(F0, __shfl_xor_sync(0xffffffffu, F0, 2));
        F0 = fmaxf(F0, __shfl_xor_sync(0xffffffffu, F0, 4));
        F0 = fmaxf(F0, __shfl_xor_sync(0xffffffffu, F0, 8));
        if (lane < 16) sw[0][c] = __expf(t - F0);
        __syncwarp();
        const float4* M4 = (const float4*)bufA;
        const float4* W4 = (const float4*)sw[0];
        float4 m0 = M4[c * 4 + 0], m1 = M4[c * 4 + 1];
        float4 m2 = M4[c * 4 + 2], m3 = M4[c * 4 + 3];
        float4 w0 = W4[0], w1 = W4[1], w2 = W4[2], w3 = W4[3];
        float d0 = fmaf(m0.x, w0.x, m0.y * w0.y) + fmaf(m0.z, w0.z, m0.w * w0.w);
        float d1 = fmaf(m1.x, w1.x, m1.y * w1.y) + fmaf(m1.z, w1.z, m1.w * w1.w);
        float d2 = fmaf(m2.x, w2.x, m2.y * w2.y) + fmaf(m2.z, w2.z, m2.w * w2.w);
        float d3 = fmaf(m3.x, w3.x, m3.y * w3.y) + fmaf(m3.z, w3.z, m3.w * w3.w);
        float v = (d0 + d1) + (d2 + d3);      // lane c: (M w)_c

        float u = stopl[((rb + (size_t)len) * 16 + (size_t)c) * 2];
        float mS = u;
        mS = fmaxf(mS, __shfl_xor_sync(0xffffffffu, mS, 1));
        mS = fmaxf(mS, __shfl_xor_sync(0xffffffffu, mS, 2));
        mS = fmaxf(mS, __shfl_xor_sync(0xffffffffu, mS, 4));
        mS = fmaxf(mS, __shfl_xor_sync(0xffffffffu, mS, 8));
        float term = __expf(u - mS) * v;
        term += __shfl_xor_sync(0xffffffffu, term, 1);
        term += __shfl_xor_sync(0xffffffffu, term, 2);
        term += __shfl_xor_sync(0xffffffffu, term, 4);
        term += __shfl_xor_sync(0xffffffffu, term, 8);
        if (lane == 0) atomicAdd(out, -(F0 + mS + __logf(term)));
    }
}

extern "C" void kernel_launch(void* const* d_in, const int* in_sizes, int n_in,
                              void* d_out, int out_size)
{
    const float* alogp   = (const float*)d_in[0];
    const float* stopl   = (const float*)d_in[1];
    const float* startl  = (const float*)d_in[2];
    const int*   actions = (const int*)d_in[3];
    const int*   lengths = (const int*)d_in[4];
    float* out = (float*)d_out;

    cudaFuncSetAttribute(hmm_combine_tree,
                         cudaFuncAttributeMaxDynamicSharedMemorySize, DYN_BYTES);

    hmm_chunk_kernel<<<(NB * NPR) / 4, 128>>>(alogp, stopl, startl, actions, lengths, out);

    // Combine with programmatic dependent launch (overlaps launch latency with
    // the chunk grid's tail). Falls back to a plain launch if PDL is rejected.
    cudaLaunchConfig_t cfg = {};
    cfg.gridDim = dim3(NB, 1, 1);
    cfg.blockDim = dim3(256, 1, 1);
    cfg.dynamicSmemBytes = DYN_BYTES;
    cfg.stream = 0;
    cudaLaunchAttribute attrs[1];
    attrs[0].id = cudaLaunchAttributeProgrammaticStreamSerialization;
    attrs[0].val.programmaticStreamSerializationAllowed = 1;
    cfg.attrs = attrs;
    cfg.numAttrs = 1;
    cudaError_t e = cudaLaunchKernelEx(&cfg, hmm_combine_tree,
                                       alogp, stopl, startl, actions, lengths, out);
    if (e != cudaSuccess) {
        hmm_combine_tree<<<NB, 256, DYN_BYTES>>>(alogp, stopl, startl, actions, lengths, out);
    }
}

// round 16
// speedup vs baseline: 1.1247x; 1.0070x over previous
#include <cuda_runtime.h>

// Problem constants (fixed by the dataset)
#define NB   64          // batch
#define T1   4097        // maxT+1
#define MAXT 4096
#define HB   16          // hidden states
#define NA   18          // actions
#define CL   64          // chunk length (steps per chunk)
#define NPR  32          // chunk-pairs per batch
#define BPB  8           // chunk blocks per batch
#define NMB  8           // block-level matrices per batch (after block fold)

// Scratch: per (batch, block) folded transfer matrix (512 steps each).
__device__ float g_mats[NB * NMB * HB * HB];   // 512 KB
__device__ float g_lam[NB * NMB * HB];

#define CP_ASYNC16(dst, src) \
    asm volatile("cp.async.cg.shared.global [%0], [%1], 16;" :: "r"(dst), "l"(src))
#define CP_COMMIT() asm volatile("cp.async.commit_group;" ::: "memory")
#define CP_WAIT0()  asm volatile("cp.async.wait_group 0;" ::: "memory")

// Prefetch bank: 8 steps of (stop.xy, start, action_logp) per lane.
struct PFB { float2 s[8]; float t[8]; float a[8]; };

__device__ __forceinline__ void load_group(
    int g0, int nact, unsigned idx16_0,
    const float2* __restrict__ stop2, const float* __restrict__ startl,
    const float* __restrict__ alogp, const int* __restrict__ sa,
    PFB& B)
{
#pragma unroll
    for (int u = 0; u < 8; ++u) {
        int t = g0 + u;
        if (t < nact) {
            unsigned idx = idx16_0 + (unsigned)t * 16u;
            B.s[u] = __ldg(stop2 + idx);                         // (beta, omb)
            B.t[u] = __ldg(startl + idx);                        // start
            B.a[u] = __ldg(alogp + idx * 18u + (unsigned)sa[t]); // action logp
        } else {
            B.s[u] = make_float2(0.f, 0.f); B.t[u] = 0.f; B.a[u] = 0.f;
        }
    }
}

// Per step i (exact linear map):
//   s     = sum_j exp(beta_j) * p[j]
//   p[k] <- exp(al_k+start_k)*s + exp(al_k+omb_k)*p[k]
// Every 4 steps: p /= s, lam += log(s)  (conditioning; p*e^lam invariant).
__device__ __forceinline__ void consume_group(
    int g0, int nsteps, int nact, int c, float* __restrict__ vb2,
    PFB& B, float (&p)[HB], float& lam)
{
#pragma unroll
    for (int u = 0; u < 8; ++u) {
        int t = g0 + u;
        if (t >= nsteps) return;   // nsteps is warp-uniform
        float eb   = __expf(B.s[u].x);
        float easv = __expf(B.a[u] + B.t[u]);
        float eaov = __expf(B.a[u] + B.s[u].y);
        float* vb = vb2 + (u & 1) * 48;
        vb[c]      = eb;
        vb[16 + c] = easv;
        vb[32 + c] = eaov;
        __syncwarp();
        const float4* EB = (const float4*)vb;
        float4 e0 = EB[0], e1 = EB[1], e2 = EB[2], e3 = EB[3];
        float t0 = fmaf(e0.x, p[0],  e0.y * p[1])  + fmaf(e0.z, p[2],  e0.w * p[3]);
        float t1 = fmaf(e1.x, p[4],  e1.y * p[5])  + fmaf(e1.z, p[6],  e1.w * p[7]);
        float t2 = fmaf(e2.x, p[8],  e2.y * p[9])  + fmaf(e2.z, p[10], e2.w * p[11]);
        float t3 = fmaf(e3.x, p[12], e3.y * p[13]) + fmaf(e3.z, p[14], e3.w * p[15]);
        float s = (t0 + t1) + (t2 + t3);
        if (t < nact) {            // uniform within each half-warp
            const float4* EA = (const float4*)(vb + 16);
            const float4* EO = (const float4*)(vb + 32);
            float4 a0 = EA[0], a1 = EA[1], a2 = EA[2], a3 = EA[3];
            float4 o0 = EO[0], o1 = EO[1], o2 = EO[2], o3 = EO[3];
            p[0]  = fmaf(o0.x, p[0],  a0.x * s);
            p[1]  = fmaf(o0.y, p[1],  a0.y * s);
            p[2]  = fmaf(o0.z, p[2],  a0.z * s);
            p[3]  = fmaf(o0.w, p[3],  a0.w * s);
            p[4]  = fmaf(o1.x, p[4],  a1.x * s);
            p[5]  = fmaf(o1.y, p[5],  a1.y * s);
            p[6]  = fmaf(o1.z, p[6],  a1.z * s);
            p[7]  = fmaf(o1.w, p[7],  a1.w * s);
            p[8]  = fmaf(o2.x, p[8],  a2.x * s);
            p[9]  = fmaf(o2.y, p[9],  a2.y * s);
            p[10] = fmaf(o2.z, p[10], a2.z * s);
            p[11] = fmaf(o2.w, p[11], a2.w * s);
            p[12] = fmaf(o3.x, p[12], a3.x * s);
            p[13] = fmaf(o3.y, p[13], a3.y * s);
            p[14] = fmaf(o3.z, p[14], a3.z * s);
            p[15] = fmaf(o3.w, p[15], a3.w * s);
            if ((t & 3) == 3) {
                float r = __fdividef(1.0f, s);
                lam += __logf(s);
#pragma unroll
                for (int k = 0; k < HB; ++k) p[k] *= r;
            }
        }
    }
}

// Tree product: C_true = A_true * P_true (A later, P earlier). All smem.
__device__ __forceinline__ void mat_product2(
    const float* __restrict__ srcM, const float* __restrict__ srcLam,
    float* __restrict__ dstM, float* __restrict__ dstLam,
    int pidx, int lane, float* __restrict__ sw)
{
    const int c = lane & 15;
    const int h = lane >> 4;                    // rows [8h, 8h+8)
    const float* Pm = srcM + (size_t)(2 * pidx) * 256;
    const float* Am = srcM + (size_t)(2 * pidx + 1) * 256;
    float lamP = srcLam[(2 * pidx) * 16 + c];
    float lamA = srcLam[(2 * pidx + 1) * 16 + c];
    float mA = lamA;
    mA = fmaxf(mA, __shfl_xor_sync(0xffffffffu, mA, 1));
    mA = fmaxf(mA, __shfl_xor_sync(0xffffffffu, mA, 2));
    mA = fmaxf(mA, __shfl_xor_sync(0xffffffffu, mA, 4));
    mA = fmaxf(mA, __shfl_xor_sync(0xffffffffu, mA, 8));
    if (lane < 16) sw[c] = __expf(lamA - mA);
    __syncwarp();
    float w[16];
#pragma unroll
    for (int j = 0; j < 16; ++j) w[j] = sw[j] * Pm[j * 16 + c];
    __syncwarp();
    float Cv[8];
#pragma unroll
    for (int k8 = 0; k8 < 8; ++k8) {
        const float4* A4 = (const float4*)(Am + (h * 8 + k8) * 16);
        float4 a0 = A4[0], a1 = A4[1], a2 = A4[2], a3 = A4[3];
        float d0 = fmaf(a0.x, w[0],  a0.y * w[1])  + fmaf(a0.z, w[2],  a0.w * w[3]);
        float d1 = fmaf(a1.x, w[4],  a1.y * w[5])  + fmaf(a1.z, w[6],  a1.w * w[7]);
        float d2 = fmaf(a2.x, w[8],  a2.y * w[9])  + fmaf(a2.z, w[10], a2.w * w[11]);
        float d3 = fmaf(a3.x, w[12], a3.y * w[13]) + fmaf(a3.z, w[14], a3.w * w[15]);
        Cv[k8] = (d0 + d1) + (d2 + d3);
    }
    float s = Cv[0];
#pragma unroll
    for (int k8 = 1; k8 < 8; ++k8) s = fmaxf(s, Cv[k8]);
    s = fmaxf(s, __shfl_xor_sync(0xffffffffu, s, 16));   // combine halves
    float r = __fdividef(1.0f, s);
#pragma unroll
    for (int k8 = 0; k8 < 8; ++k8)
        dstM[pidx * 256 + (h * 8 + k8) * 16 + c] = Cv[k8] * r;
    if (lane < 16) dstLam[pidx * 16 + c] = lamP + mA + __logf(s);
}

// One warp handles TWO adjacent chunks and folds them; the block then folds
// its 4 warp-matrices into ONE block-matrix (2 more levels, in smem).
__global__ __launch_bounds__(128) void hmm_chunk_kernel(
    const float* __restrict__ alogp,
    const float* __restrict__ stopl,
    const float* __restrict__ startl,
    const int* __restrict__ actions,
    const int* __restrict__ lengths,
    float* __restrict__ out)
{
    if (blockIdx.x == 0 && threadIdx.x == 0) *out = 0.0f;

    const int wib  = threadIdx.x >> 5;
    const int lane = threadIdx.x & 31;
    const int b    = blockIdx.x >> 3;          // 64 batches
    const int blk  = blockIdx.x & 7;           // 8 blocks per batch
    const int pr   = blk * 4 + wib;            // 32 chunk-pairs per batch
    const int sub  = lane >> 4;
    const int c    = lane & 15;
    const int ch   = pr * 2 + sub;
    const int i0   = 1 + ch * CL;

    __shared__ int s_act[4][2 * CL];
    __shared__ __align__(16) float s_vec[4][2][2][3 * HB];
    __shared__ __align__(16) float s_m1[4][HB][HB + 1];
    __shared__ float s_lam1[4][HB];
    __shared__ __align__(16) float bm[6 * 256];
    __shared__ float lamB[6 * 16];
    __shared__ __align__(16) float sw[4][16];

    const int len = lengths[b];

    int cnt  = min(CL, MAXT - i0);
    int nact = max(0, min(len - i0, cnt));
    const int i0p  = 1 + pr * 2 * CL;
    int n0 = max(0, min(len - i0p, min(CL, MAXT - i0p)));
    int n1 = max(0, min(len - (i0p + CL), min(CL, MAXT - (i0p + CL))));
    int nsteps = max(n0, n1);

    int totA = min(2 * CL, MAXT - i0p);
    for (int idx = lane; idx < totA; idx += 32)
        s_act[wib][idx] = actions[(size_t)b * MAXT + i0p + idx];
    __syncwarp();

    float p[HB];
#pragma unroll
    for (int k = 0; k < HB; ++k) p[k] = (k == c) ? 1.0f : 0.0f;
    float lam = 0.0f;

    if (nsteps > 0) {
        const unsigned idx16_0 = ((unsigned)b * T1 + (unsigned)i0) * 16u + (unsigned)c;
        const float2* stop2 = (const float2*)stopl;
        const int* sa = &s_act[wib][sub * CL];
        float* vb2 = &s_vec[wib][sub][0][0];

        PFB B0, B1;
        load_group(0, nact, idx16_0, stop2, startl, alogp, sa, B0);
        for (int g0 = 0; g0 < nsteps; g0 += 16) {
            load_group(g0 + 8, nact, idx16_0, stop2, startl, alogp, sa, B1);
            consume_group(g0, nsteps, nact, c, vb2, B0, p, lam);
            if (g0 + 8 < nsteps) {
                load_group(g0 + 16, nact, idx16_0, stop2, startl, alogp, sa, B0);
                consume_group(g0 + 8, nsteps, nact, c, vb2, B1, p, lam);
            }
        }
    }

    // Warp fold: R_true = M1_true * M0_true -> smem bm[wib]
    __syncwarp();
    if (sub == 1) {
#pragma unroll
        for (int k = 0; k < HB; ++k) s_m1[wib][c][k] = p[k];   // row c = column c of M1hat
        s_lam1[wib][c] = lam;
    }
    __syncwarp();
    if (sub == 0) {
        float m1 = s_lam1[wib][0];
#pragma unroll
        for (int j = 1; j < HB; ++j) m1 = fmaxf(m1, s_lam1[wib][j]);
        float R[HB];
#pragma unroll
        for (int k = 0; k < HB; ++k) R[k] = 0.0f;
#pragma unroll
        for (int j = 0; j < HB; ++j) {
            float wj = p[j] * __expf(s_lam1[wib][j] - m1);
            const float* Aj = &s_m1[wib][j][0];
#pragma unroll
            for (int k = 0; k < HB; ++k) R[k] = fmaf(wj, Aj[k], R[k]);
        }
        float s = R[0];
#pragma unroll
        for (int k = 1; k < HB; ++k) s = fmaxf(s, R[k]);
        float r = __fdividef(1.0f, s);
#pragma unroll
        for (int k = 0; k < HB; ++k)
            bm[wib * 256 + k * 16 + c] = R[k] * r;
        lamB[wib * 16 + c] = lam + m1 + __logf(s);
    }
    __syncthreads();

    // Block fold: 4 warp-mats -> 2 -> 1 -> gmem (time order = wib order)
    if (wib < 2)
        mat_product2(bm, lamB, bm + 4 * 256, lamB + 4 * 16, wib, lane, sw[wib]);
    __syncthreads();
    if (wib == 0) {
        __shared__ __align__(16) float fin[256];
        __shared__ float finLam[16];
        mat_product2(bm + 4 * 256, lamB + 4 * 16, fin, finLam, 0, lane, sw[0]);
        float* gm = g_mats + (size_t)(b * NMB + blk) * 256;
#pragma unroll
        for (int k8 = 0; k8 < 8; ++k8)
            gm[((lane >> 4) * 8 + k8) * 16 + c] = fin[((lane >> 4) * 8 + k8) * 16 + c];
        if (lane < 16)
            g_lam[(size_t)(b * NMB + blk) * 16 + c] = finLam[c];
    }

    // PDL: results are in gmem -> let the dependent (combine) grid launch.
    __threadfence();
    asm volatile("griddepcontrol.launch_dependents;" ::: "memory");
}

// ---------------------------------------------------------------------------
// Tree combine: one block (4 warps, 128 thr) per batch; 3 levels over 8 mats,
// all in smem after one cp.async staging shot.
// ---------------------------------------------------------------------------
#define DYN_FLOATS (NMB * 256 + NMB * 16)
#define DYN_BYTES  (DYN_FLOATS * 4)

__global__ __launch_bounds__(128, 1) void hmm_combine_tree(
    const float* __restrict__ alogp,
    const float* __restrict__ stopl,
    const float* __restrict__ startl,
    const int* __restrict__ actions,
    const int* __restrict__ lengths,
    float* __restrict__ out)
{
    extern __shared__ __align__(16) float dyn[];
    __shared__ __align__(16) float bufA[4 * 256];
    __shared__ float lamA[4 * 16];
    __shared__ __align__(16) float sw[4][16];

    const int b    = blockIdx.x;
    const int warp = threadIdx.x >> 5;
    const int lane = threadIdx.x & 31;
    const int tid  = threadIdx.x;

    // With PDL this waits for the chunk grid's results; no-op on plain launch.
    asm volatile("griddepcontrol.wait;" ::: "memory");

    // Stage the 8 matrices + lams into smem (coalesced, one latency shot).
    const float* gM = g_mats + (size_t)b * NMB * 256;
    const float* gL = g_lam  + (size_t)b * NMB * 16;
    unsigned sbase = (unsigned)__cvta_generic_to_shared(dyn);
    for (int i = tid; i < (NMB * 256) / 4; i += 128)
        CP_ASYNC16(sbase + (unsigned)i * 16u, ((const float4*)gM) + i);
    for (int i = tid; i < (NMB * 16) / 4; i += 128)
        CP_ASYNC16(sbase + (unsigned)(NMB * 256 * 4) + (unsigned)i * 16u, ((const float4*)gL) + i);
    CP_COMMIT();
    CP_WAIT0();
    __syncthreads();

    float* sM = dyn;                 // 8 mats (dead after L1 -> reused as bufB)
    float* sL = dyn + NMB * 256;     // 8 lams (dead after L1 -> reused as lamB)
    float* bufB = dyn;               // 2 mats max
    float* lamB = dyn + NMB * 256;

    // L1: 8 -> 4 (smem -> bufA)
    mat_product2(sM, sL, bufA, lamA, warp, lane, sw[warp]);
    __syncthreads();
    // L2: 4 -> 2 (bufA -> bufB; staged area dead)
    if (warp < 2) mat_product2(bufA, lamA, bufB, lamB, warp, lane, sw[warp]);
    __syncthreads();
    // L3: 2 -> 1 (final in bufA[0], lam in lamA[0..15])
    if (warp == 0) mat_product2(bufB, lamB, bufA, lamA, 0, lane, sw[0]);
    __syncthreads();

    if (warp == 0) {
        const int c = lane & 15;
        const int len = lengths[b];
        const size_t rb = (size_t)b * T1;
        const int a0i = actions[(size_t)b * MAXT];

        float f0 = startl[rb * 16 + c] + alogp[(rb * 16 + (size_t)c) * 18 + a0i];
        float t = lamA[c] + f0;
        float F0 = t;
        F0 = fmaxf(F0, __shfl_xor_sync(0xffffffffu, F0, 1));
        F0 = fmaxf(F0, __shfl_xor_sync(0xffffffffu, F0, 2));
        F0 = fmaxf(F0, __shfl_xor_sync(0xffffffffu, F0, 4));
        F0 = fmaxf(F0, __shfl_xor_sync(0xffffffffu, F0, 8));
        if (lane < 16) sw[0][c] = __expf(t - F0);
        __syncwarp();
        const float4* M4 = (const float4*)bufA;
        const float4* W4 = (const float4*)sw[0];
        float4 m0 = M4[c * 4 + 0], m1 = M4[c * 4 + 1];
        float4 m2 = M4[c * 4 + 2], m3 = M4[c * 4 + 3];
        float4 w0 = W4[0], w1 = W4[1], w2 = W4[2], w3 = W4[3];
        float d0 = fmaf(m0.x, w0.x, m0.y * w0.y) + fmaf(m0.z, w0.z, m0.w * w0.w);
        float d1 = fmaf(m1.x, w1.x, m1.y * w1.y) + fmaf(m1.z, w1.z, m1.w * w1.w);
        float d2 = fmaf(m2.x, w2.x, m2.y * w2.y) + fmaf(m2.z, w2.z, m2.w * w2.w);
        float d3 = fmaf(m3.x, w3.x, m3.y * w3.y) + fmaf(m3.z, w3.z, m3.w * w3.w);
        float v = (d0 + d1) + (d2 + d3);      // lane c: (M w)_c

        float u = stopl[((rb + (size_t)len) * 16 + (size_t)c) * 2];
        float mS = u;
        mS = fmaxf(mS, __shfl_xor_sync(0xffffffffu, mS, 1));
        mS = fmaxf(mS, __shfl_xor_sync(0xffffffffu, mS, 2));
        mS = fmaxf(mS, __shfl_xor_sync(0xffffffffu, mS, 4));
        mS = fmaxf(mS, __shfl_xor_sync(0xffffffffu, mS, 8));
        float term = __expf(u - mS) * v;
        term += __shfl_xor_sync(0xffffffffu, term, 1);
        term += __shfl_xor_sync(0xffffffffu, term, 2);
        term += __shfl_xor_sync(0xffffffffu, term, 4);
        term += __shfl_xor_sync(0xffffffffu, term, 8);
        if (lane == 0) atomicAdd(out, -(F0 + mS + __logf(term)));
    }
}

extern "C" void kernel_launch(void* const* d_in, const int* in_sizes, int n_in,
                              void* d_out, int out_size)
{
    const float* alogp   = (const float*)d_in[0];
    const float* stopl   = (const float*)d_in[1];
    const float* startl  = (const float*)d_in[2];
    const int*   actions = (const int*)d_in[3];
    const int*   lengths = (const int*)d_in[4];
    float* out = (float*)d_out;

    cudaFuncSetAttribute(hmm_combine_tree,
                         cudaFuncAttributeMaxDynamicSharedMemorySize, DYN_BYTES);

    hmm_chunk_kernel<<<NB * BPB, 128>>>(alogp, stopl, startl, actions, lengths, out);

    // Combine with programmatic dependent launch; plain-launch fallback.
    cudaLaunchConfig_t cfg = {};
    cfg.gridDim = dim3(NB, 1, 1);
    cfg.blockDim = dim3(128, 1, 1);
    cfg.dynamicSmemBytes = DYN_BYTES;
    cfg.stream = 0;
    cudaLaunchAttribute attrs[1];
    attrs[0].id = cudaLaunchAttributeProgrammaticStreamSerialization;
    attrs[0].val.programmaticStreamSerializationAllowed = 1;
    cfg.attrs = attrs;
    cfg.numAttrs = 1;
    cudaError_t e = cudaLaunchKernelEx(&cfg, hmm_combine_tree,
                                       alogp, stopl, startl, actions, lengths, out);
    if (e != cudaSuccess) {
        hmm_combine_tree<<<NB, 128, DYN_BYTES>>>(alogp, stopl, startl, actions, lengths, out);
    }
}